// round 1
// baseline (speedup 1.0000x reference)
#include <cuda_runtime.h>
#include <math.h>

#define NB 4
#define NS 2048
#define NE 1024

// Scratch: device globals (no cudaMalloc allowed).
__device__ float g_Q[NB * NS * NE];          // 32 MB
__device__ float g_K[NB * NS * NE];          // 32 MB
__device__ float g_V[NB * NS * NE];          // 32 MB
__device__ float g_P[(size_t)NB * NS * NS];  // 64 MB

// ---------------------------------------------------------------------------
// Tiled SGEMM: C = alpha * A @ op(B) (+ bias), 128x128x16 tiles, 8x8/thread.
// A: [M,K] row-major. TRANSB: B is [N,K] row-major (C=A*B^T); else B is [K,N].
// Batched via blockIdx.z with element strides. M,N multiples of 128; K of 16.
// ---------------------------------------------------------------------------
template <bool TRANSB, bool HASBIAS>
__global__ __launch_bounds__(256, 2)
void gemm128(const float* __restrict__ A, const float* __restrict__ Bm,
             const float* __restrict__ bias, float* __restrict__ C,
             int M, int N, int K,
             long long strideA, long long strideB, long long strideC,
             float alpha)
{
    const int BM = 128, BN = 128, BK = 16;
    __shared__ float sA[BK][BM + 4];
    __shared__ float sB[BK][BN + 4];

    const int tid = threadIdx.x;
    const int tx = tid & 15;   // 0..15 (N direction)
    const int ty = tid >> 4;   // 0..15 (M direction)

    const float* Ab = A + (long long)blockIdx.z * strideA
                        + (long long)(blockIdx.y * BM) * K;
    const float* Bb;
    if (TRANSB)
        Bb = Bm + (long long)blockIdx.z * strideB
                + (long long)(blockIdx.x * BN) * K;
    else
        Bb = Bm + (long long)blockIdx.z * strideB + blockIdx.x * BN;

    float acc[8][8];
#pragma unroll
    for (int i = 0; i < 8; i++)
#pragma unroll
        for (int j = 0; j < 8; j++) acc[i][j] = 0.f;

    // K-major tile load indices (A, and B when TRANSB): 128 rows x 16 k
    const int aRow = tid >> 2;        // 0..63
    const int aCol = (tid & 3) << 2;  // 0,4,8,12
    // N-major tile load indices (B when !TRANSB): 16 k x 128 n
    const int bRow = tid >> 5;        // 0..7
    const int bCol = (tid & 31) << 2; // 0..124

    for (int kt = 0; kt < K; kt += BK) {
#pragma unroll
        for (int r = 0; r < 2; r++) {
            const float4 v = *(const float4*)(Ab + (long long)(aRow + r * 64) * K + (kt + aCol));
            sA[aCol + 0][aRow + r * 64] = v.x;
            sA[aCol + 1][aRow + r * 64] = v.y;
            sA[aCol + 2][aRow + r * 64] = v.z;
            sA[aCol + 3][aRow + r * 64] = v.w;
        }
        if (TRANSB) {
#pragma unroll
            for (int r = 0; r < 2; r++) {
                const float4 v = *(const float4*)(Bb + (long long)(aRow + r * 64) * K + (kt + aCol));
                sB[aCol + 0][aRow + r * 64] = v.x;
                sB[aCol + 1][aRow + r * 64] = v.y;
                sB[aCol + 2][aRow + r * 64] = v.z;
                sB[aCol + 3][aRow + r * 64] = v.w;
            }
        } else {
#pragma unroll
            for (int r = 0; r < 2; r++) {
                const float4 v = *(const float4*)(Bb + (long long)(kt + bRow + r * 8) * N + bCol);
                *(float4*)(&sB[bRow + r * 8][bCol]) = v;
            }
        }
        __syncthreads();

#pragma unroll
        for (int k = 0; k < BK; k++) {
            const float4 a0 = *(const float4*)(&sA[k][ty * 8]);
            const float4 a1 = *(const float4*)(&sA[k][ty * 8 + 4]);
            const float4 b0 = *(const float4*)(&sB[k][tx * 8]);
            const float4 b1 = *(const float4*)(&sB[k][tx * 8 + 4]);
            const float af[8] = {a0.x, a0.y, a0.z, a0.w, a1.x, a1.y, a1.z, a1.w};
            const float bf[8] = {b0.x, b0.y, b0.z, b0.w, b1.x, b1.y, b1.z, b1.w};
#pragma unroll
            for (int i = 0; i < 8; i++)
#pragma unroll
                for (int j = 0; j < 8; j++)
                    acc[i][j] = fmaf(af[i], bf[j], acc[i][j]);
        }
        __syncthreads();
    }

    float* Cb = C + (long long)blockIdx.z * strideC;
    const int row0 = blockIdx.y * BM + ty * 8;
    const int col0 = blockIdx.x * BN + tx * 8;

    float bias_f[8];
    if (HASBIAS) {
#pragma unroll
        for (int j = 0; j < 8; j++) bias_f[j] = bias[col0 + j];
    }

#pragma unroll
    for (int i = 0; i < 8; i++) {
        float4 o0, o1;
        o0.x = acc[i][0] * alpha; o0.y = acc[i][1] * alpha;
        o0.z = acc[i][2] * alpha; o0.w = acc[i][3] * alpha;
        o1.x = acc[i][4] * alpha; o1.y = acc[i][5] * alpha;
        o1.z = acc[i][6] * alpha; o1.w = acc[i][7] * alpha;
        if (HASBIAS) {
            o0.x += bias_f[0]; o0.y += bias_f[1]; o0.z += bias_f[2]; o0.w += bias_f[3];
            o1.x += bias_f[4]; o1.y += bias_f[5]; o1.z += bias_f[6]; o1.w += bias_f[7];
        }
        *(float4*)(Cb + (long long)(row0 + i) * N + col0)     = o0;
        *(float4*)(Cb + (long long)(row0 + i) * N + col0 + 4) = o1;
    }
}

// ---------------------------------------------------------------------------
// Row softmax over rows of length NS (=2048). One block (256 thr) per row.
// ---------------------------------------------------------------------------
__global__ __launch_bounds__(256)
void softmax2048(float* __restrict__ P)
{
    __shared__ float red[32];
    float* p = P + (long long)blockIdx.x * NS;
    const int tid = threadIdx.x;

    float v[8];
#pragma unroll
    for (int i = 0; i < 8; i++) v[i] = p[tid + i * 256];

    float m = v[0];
#pragma unroll
    for (int i = 1; i < 8; i++) m = fmaxf(m, v[i]);
#pragma unroll
    for (int o = 16; o > 0; o >>= 1) m = fmaxf(m, __shfl_xor_sync(0xffffffffu, m, o));
    if ((tid & 31) == 0) red[tid >> 5] = m;
    __syncthreads();
    if (tid < 32) {
        float t = (tid < 8) ? red[tid] : -INFINITY;
#pragma unroll
        for (int o = 4; o > 0; o >>= 1) t = fmaxf(t, __shfl_xor_sync(0xffffffffu, t, o));
        if (tid == 0) red[0] = t;
    }
    __syncthreads();
    m = red[0];
    __syncthreads();

    float s = 0.f;
#pragma unroll
    for (int i = 0; i < 8; i++) { v[i] = __expf(v[i] - m); s += v[i]; }
#pragma unroll
    for (int o = 16; o > 0; o >>= 1) s += __shfl_xor_sync(0xffffffffu, s, o);
    if ((tid & 31) == 0) red[tid >> 5] = s;
    __syncthreads();
    if (tid < 32) {
        float t = (tid < 8) ? red[tid] : 0.f;
#pragma unroll
        for (int o = 4; o > 0; o >>= 1) t += __shfl_xor_sync(0xffffffffu, t, o);
        if (tid == 0) red[0] = t;
    }
    __syncthreads();
    const float inv = 1.f / red[0];
#pragma unroll
    for (int i = 0; i < 8; i++) p[tid + i * 256] = v[i] * inv;
}

// ---------------------------------------------------------------------------
// Launcher. Pipeline:
//   K,Q,V = X @ W^T + b              (3x NT GEMM, M=8192 N=K=1024)
//   P[b,j,i] = (Q_j . K_i)/sqrt(S)   (batched NT GEMM)   [= scores transposed]
//   softmax over last axis of P      (== reference softmax over axis=-2)
//   Y = P @ V                        (batched NN GEMM)
// ---------------------------------------------------------------------------
extern "C" void kernel_launch(void* const* d_in, const int* in_sizes, int n_in,
                              void* d_out, int out_size)
{
    const float* X  = (const float*)d_in[0];
    const float* Wk = (const float*)d_in[1];
    const float* bk = (const float*)d_in[2];
    const float* Wq = (const float*)d_in[3];
    const float* bq = (const float*)d_in[4];
    const float* Wv = (const float*)d_in[5];
    const float* bv = (const float*)d_in[6];
    float* Y = (float*)d_out;

    float *Qp, *Kp, *Vp, *Pp;
    cudaGetSymbolAddress((void**)&Qp, g_Q);
    cudaGetSymbolAddress((void**)&Kp, g_K);
    cudaGetSymbolAddress((void**)&Vp, g_V);
    cudaGetSymbolAddress((void**)&Pp, g_P);

    const dim3 blk(256);

    // Projections: M = B*S = 8192, N = K = E
    {
        dim3 grid(NE / 128, (NB * NS) / 128, 1);
        gemm128<true, true><<<grid, blk>>>(X, Wk, bk, Kp, NB * NS, NE, NE, 0, 0, 0, 1.f);
        gemm128<true, true><<<grid, blk>>>(X, Wq, bq, Qp, NB * NS, NE, NE, 0, 0, 0, 1.f);
        gemm128<true, true><<<grid, blk>>>(X, Wv, bv, Vp, NB * NS, NE, NE, 0, 0, 0, 1.f);
    }

    // Scores (transposed): P[b,j,i] = Q_j . K_i * 1/sqrt(S)
    {
        dim3 grid(NS / 128, NS / 128, NB);
        const float alpha = 1.f / sqrtf((float)NS);
        gemm128<true, false><<<grid, blk>>>(Qp, Kp, nullptr, Pp, NS, NS, NE,
                                            (long long)NS * NE, (long long)NS * NE,
                                            (long long)NS * NS, alpha);
    }

    // Softmax over last axis (key index i)
    softmax2048<<<NB * NS, 256>>>(Pp);

    // Y = P @ V
    {
        dim3 grid(NE / 128, NS / 128, NB);
        gemm128<false, false><<<grid, blk>>>(Pp, Vp, nullptr, Y, NS, NE, NS,
                                             (long long)NS * NS, (long long)NS * NE,
                                             (long long)NS * NE, 1.f);
    }
}

// round 3
// speedup vs baseline: 1.4882x; 1.4882x over previous
#include <cuda_runtime.h>
#include <cuda_bf16.h>
#include <math.h>
#include <stdint.h>

#define NB 4
#define NS 2048
#define NE 1024

// Scratch (no cudaMalloc allowed)
__device__ float g_Q[NB * NS * NE];           // 32 MB
__device__ float g_K[NB * NS * NE];           // 32 MB
__device__ float g_Vt[(size_t)NE * NB * NS];  // 32 MB  [E, B*S]
__device__ float g_P[(size_t)NB * NS * NS];   // 64 MB

__device__ __forceinline__ uint32_t smem_u32(const void* p) {
    uint32_t a;
    asm("{ .reg .u64 t; cvta.to.shared.u64 t, %1; cvt.u32.u64 %0, t; }" : "=r"(a) : "l"(p));
    return a;
}

__device__ __forceinline__ void ldsm4(uint32_t* r, uint32_t addr) {
    asm volatile("ldmatrix.sync.aligned.m8n8.x4.shared.b16 {%0,%1,%2,%3}, [%4];"
                 : "=r"(r[0]), "=r"(r[1]), "=r"(r[2]), "=r"(r[3]) : "r"(addr));
}

__device__ __forceinline__ void mma16816(float* c, const uint32_t* a, const uint32_t* b) {
    asm volatile("mma.sync.aligned.m16n8k16.row.col.f32.bf16.bf16.f32 "
                 "{%0,%1,%2,%3}, {%4,%5,%6,%7}, {%8,%9}, {%0,%1,%2,%3};"
                 : "+f"(c[0]), "+f"(c[1]), "+f"(c[2]), "+f"(c[3])
                 : "r"(a[0]), "r"(a[1]), "r"(a[2]), "r"(a[3]), "r"(b[0]), "r"(b[1]));
}

// bf16 pack helpers (unambiguous element order: a -> low 16, b -> high 16)
__device__ __forceinline__ uint32_t pack_bf2(float a, float b) {
    unsigned short ua = __bfloat16_as_ushort(__float2bfloat16(a));
    unsigned short ub = __bfloat16_as_ushort(__float2bfloat16(b));
    return (uint32_t)ua | ((uint32_t)ub << 16);
}

// smem tile geometry: 128 rows x 32 bf16, padded to 40 bf16 (80 B) per row.
#define ROWB 80
#define T_A_HI 0
#define T_A_LO 10240
#define T_B_HI 20480
#define T_B_LO 30720
#define STAGE  40960
#define SMEM_TOTAL (2 * STAGE)

// ---------------------------------------------------------------------------
// HMMA GEMM: C[M,N] = alpha * A[M,K] * B[N,K]^T (+bias). Both K-major (NT).
// 128x128 tile, BK=32, bf16 hi/lo 3-term split, double-buffered smem.
// BIAS: 0 none, 1 bias[col], 2 bias[row].
// ---------------------------------------------------------------------------
template <int BIAS>
__global__ void __launch_bounds__(256, 1)
tcgemm(const float* __restrict__ A, const float* __restrict__ B,
       const float* __restrict__ bias, float* __restrict__ C,
       int lda, int ldb, int ldc, int Kdim,
       long long sA, long long sB, long long sC, float alpha)
{
    extern __shared__ char smem[];
    const uint32_t sb = smem_u32(smem);
    const int tid = threadIdx.x;
    const int lane = tid & 31;
    const int wid = tid >> 5;
    const int warpM = (wid & 3) * 32;    // 4 warps in M
    const int warpN = (wid >> 2) * 64;   // 2 warps in N

    const float* Ab = A + (long long)blockIdx.z * sA + (long long)(blockIdx.y * 128) * lda;
    const float* Bb = B + (long long)blockIdx.z * sB + (long long)(blockIdx.x * 128) * ldb;

    float acc[2][8][4];
#pragma unroll
    for (int m = 0; m < 2; m++)
#pragma unroll
        for (int n = 0; n < 8; n++)
#pragma unroll
            for (int q = 0; q < 4; q++) acc[m][n][q] = 0.f;

    float4 stash[8];   // 4 float4 A + 4 float4 B per thread per stage

    // linear mapping: idx = tid + p*256 -> row = idx>>3, colq = idx&7 (float4)
    auto ldgStage = [&](int kt) {
#pragma unroll
        for (int p = 0; p < 4; p++) {
            const int idx = tid + p * 256;
            const int r = idx >> 3, cq = idx & 7;
            stash[p]     = *(const float4*)(Ab + (long long)r * lda + kt + cq * 4);
            stash[p + 4] = *(const float4*)(Bb + (long long)r * ldb + kt + cq * 4);
        }
    };

    auto cvtStore = [&](char* hi, char* lo, int r, int cq, float4 v) {
        const uint32_t off = (uint32_t)(r * ROWB + cq * 8);
        const uint32_t h01 = pack_bf2(v.x, v.y);
        const uint32_t h23 = pack_bf2(v.z, v.w);
        const float hx = __uint_as_float(h01 << 16);
        const float hy = __uint_as_float(h01 & 0xFFFF0000u);
        const float hz = __uint_as_float(h23 << 16);
        const float hw = __uint_as_float(h23 & 0xFFFF0000u);
        const uint32_t l01 = pack_bf2(v.x - hx, v.y - hy);
        const uint32_t l23 = pack_bf2(v.z - hz, v.w - hw);
        *(uint2*)(hi + off) = make_uint2(h01, h23);
        *(uint2*)(lo + off) = make_uint2(l01, l23);
    };

    auto stsStage = [&](int s) {
        char* st = smem + s * STAGE;
#pragma unroll
        for (int p = 0; p < 4; p++) {
            const int idx = tid + p * 256;
            const int r = idx >> 3, cq = idx & 7;
            cvtStore(st + T_A_HI, st + T_A_LO, r, cq, stash[p]);
            cvtStore(st + T_B_HI, st + T_B_LO, r, cq, stash[p + 4]);
        }
    };

    const uint32_t rA = (uint32_t)(warpM + (lane & 15));
    const uint32_t rB = (uint32_t)(warpN + (lane & 15));

    auto compute = [&](int s) {
        const uint32_t stb = sb + s * STAGE;
#pragma unroll
        for (int kh = 0; kh < 2; kh++) {
            const uint32_t cb = ((lane >> 4) * 8 + kh * 16) * 2;  // byte col offset
            uint32_t ahi[2][4], alo[2][4], bhi[8][2], blo[8][2];
#pragma unroll
            for (int mt = 0; mt < 2; mt++) {
                ldsm4(ahi[mt], stb + T_A_HI + (rA + mt * 16) * ROWB + cb);
                ldsm4(alo[mt], stb + T_A_LO + (rA + mt * 16) * ROWB + cb);
            }
#pragma unroll
            for (int np = 0; np < 4; np++) {
                uint32_t t[4];
                ldsm4(t, stb + T_B_HI + (rB + np * 16) * ROWB + cb);
                bhi[2 * np][0] = t[0]; bhi[2 * np][1] = t[2];
                bhi[2 * np + 1][0] = t[1]; bhi[2 * np + 1][1] = t[3];
                ldsm4(t, stb + T_B_LO + (rB + np * 16) * ROWB + cb);
                blo[2 * np][0] = t[0]; blo[2 * np][1] = t[2];
                blo[2 * np + 1][0] = t[1]; blo[2 * np + 1][1] = t[3];
            }
#pragma unroll
            for (int mt = 0; mt < 2; mt++)
#pragma unroll
                for (int nt = 0; nt < 8; nt++) {
                    mma16816(acc[mt][nt], ahi[mt], bhi[nt]);
                    mma16816(acc[mt][nt], ahi[mt], blo[nt]);
                    mma16816(acc[mt][nt], alo[mt], bhi[nt]);
                }
        }
    };

    const int CH = Kdim >> 5;
    ldgStage(0);
    stsStage(0);
    __syncthreads();

    for (int c = 0; c < CH; c++) {
        if (c + 1 < CH) ldgStage((c + 1) * 32);
        compute(c & 1);
        if (c + 1 < CH) stsStage((c + 1) & 1);
        __syncthreads();
    }

    // epilogue
    float* Cb = C + (long long)blockIdx.z * sC;
    const int g = lane >> 2, tg = lane & 3;
#pragma unroll
    for (int mt = 0; mt < 2; mt++) {
        const int row = blockIdx.y * 128 + warpM + mt * 16 + g;
        float rb0 = 0.f, rb8 = 0.f;
        if (BIAS == 2) { rb0 = bias[row]; rb8 = bias[row + 8]; }
#pragma unroll
        for (int nt = 0; nt < 8; nt++) {
            const int col = blockIdx.x * 128 + warpN + nt * 8 + tg * 2;
            float b0 = 0.f, b1 = 0.f;
            if (BIAS == 1) { b0 = bias[col]; b1 = bias[col + 1]; }
            float c0 = acc[mt][nt][0] * alpha;
            float c1 = acc[mt][nt][1] * alpha;
            float c2 = acc[mt][nt][2] * alpha;
            float c3 = acc[mt][nt][3] * alpha;
            if (BIAS == 1) { c0 += b0; c1 += b1; c2 += b0; c3 += b1; }
            if (BIAS == 2) { c0 += rb0; c1 += rb0; c2 += rb8; c3 += rb8; }
            *(float2*)(Cb + (long long)row * ldc + col)       = make_float2(c0, c1);
            *(float2*)(Cb + (long long)(row + 8) * ldc + col) = make_float2(c2, c3);
        }
    }
}

// ---------------------------------------------------------------------------
// Row softmax over rows of length NS (=2048). One block (256 thr) per row.
// ---------------------------------------------------------------------------
__global__ __launch_bounds__(256)
void softmax2048(float* __restrict__ P)
{
    __shared__ float red[32];
    float* p = P + (long long)blockIdx.x * NS;
    const int tid = threadIdx.x;

    float v[8];
#pragma unroll
    for (int i = 0; i < 8; i++) v[i] = p[tid + i * 256];

    float m = v[0];
#pragma unroll
    for (int i = 1; i < 8; i++) m = fmaxf(m, v[i]);
#pragma unroll
    for (int o = 16; o > 0; o >>= 1) m = fmaxf(m, __shfl_xor_sync(0xffffffffu, m, o));
    if ((tid & 31) == 0) red[tid >> 5] = m;
    __syncthreads();
    if (tid < 32) {
        float t = (tid < 8) ? red[tid] : -INFINITY;
#pragma unroll
        for (int o = 4; o > 0; o >>= 1) t = fmaxf(t, __shfl_xor_sync(0xffffffffu, t, o));
        if (tid == 0) red[0] = t;
    }
    __syncthreads();
    m = red[0];
    __syncthreads();

    float s = 0.f;
#pragma unroll
    for (int i = 0; i < 8; i++) { v[i] = __expf(v[i] - m); s += v[i]; }
#pragma unroll
    for (int o = 16; o > 0; o >>= 1) s += __shfl_xor_sync(0xffffffffu, s, o);
    if ((tid & 31) == 0) red[tid >> 5] = s;
    __syncthreads();
    if (tid < 32) {
        float t = (tid < 8) ? red[tid] : 0.f;
#pragma unroll
        for (int o = 4; o > 0; o >>= 1) t += __shfl_xor_sync(0xffffffffu, t, o);
        if (tid == 0) red[0] = t;
    }
    __syncthreads();
    const float inv = 1.f / red[0];
#pragma unroll
    for (int i = 0; i < 8; i++) p[tid + i * 256] = v[i] * inv;
}

// ---------------------------------------------------------------------------
// Launcher.
//   K = X @ Wk^T + bk           tcgemm<1>  (col bias)
//   Q = X @ Wq^T + bq           tcgemm<1>
//   Vt = Wv @ X^T + bv(row)     tcgemm<2>  -> Vt [E, B*S]
//   P[b,j,i] = Qj.Ki / sqrt(S)  tcgemm<0>  (batched)
//   softmax over i
//   Y = P @ Vt^T                tcgemm<0>  (batched)
// ---------------------------------------------------------------------------
extern "C" void kernel_launch(void* const* d_in, const int* in_sizes, int n_in,
                              void* d_out, int out_size)
{
    const float* X  = (const float*)d_in[0];
    const float* Wk = (const float*)d_in[1];
    const float* bk = (const float*)d_in[2];
    const float* Wq = (const float*)d_in[3];
    const float* bq = (const float*)d_in[4];
    const float* Wv = (const float*)d_in[5];
    const float* bv = (const float*)d_in[6];
    float* Y = (float*)d_out;

    float *Qp, *Kp, *Vtp, *Pp;
    cudaGetSymbolAddress((void**)&Qp, g_Q);
    cudaGetSymbolAddress((void**)&Kp, g_K);
    cudaGetSymbolAddress((void**)&Vtp, g_Vt);
    cudaGetSymbolAddress((void**)&Pp, g_P);

    cudaFuncSetAttribute(tcgemm<0>, cudaFuncAttributeMaxDynamicSharedMemorySize, SMEM_TOTAL);
    cudaFuncSetAttribute(tcgemm<1>, cudaFuncAttributeMaxDynamicSharedMemorySize, SMEM_TOTAL);
    cudaFuncSetAttribute(tcgemm<2>, cudaFuncAttributeMaxDynamicSharedMemorySize, SMEM_TOTAL);

    const dim3 blk(256);
    const int BSN = NB * NS;  // 8192

    // K, Q projections: M=8192, N=1024, K=1024
    {
        dim3 grid(NE / 128, BSN / 128, 1);
        tcgemm<1><<<grid, blk, SMEM_TOTAL>>>(X, Wk, bk, Kp, NE, NE, NE, NE, 0, 0, 0, 1.f);
        tcgemm<1><<<grid, blk, SMEM_TOTAL>>>(X, Wq, bq, Qp, NE, NE, NE, NE, 0, 0, 0, 1.f);
    }
    // Vt = Wv @ X^T + bv(row): M=1024, N=8192, K=1024
    {
        dim3 grid(BSN / 128, NE / 128, 1);
        tcgemm<2><<<grid, blk, SMEM_TOTAL>>>(Wv, X, bv, Vtp, NE, NE, BSN, NE, 0, 0, 0, 1.f);
    }
    // Scores: P[b,j,i] = Q_j . K_i / sqrt(S): M=N=2048, K=1024, batched
    {
        dim3 grid(NS / 128, NS / 128, NB);
        const float alpha = rsqrtf((float)NS);
        tcgemm<0><<<grid, blk, SMEM_TOTAL>>>(Qp, Kp, nullptr, Pp, NE, NE, NS, NE,
                                             (long long)NS * NE, (long long)NS * NE,
                                             (long long)NS * NS, alpha);
    }
    // Softmax over key index i
    softmax2048<<<NB * NS, 256>>>(Pp);

    // Y = P @ Vt^T: M=2048, N=1024, K=2048
    {
        dim3 grid(NE / 128, NS / 128, NB);
        tcgemm<0><<<grid, blk, SMEM_TOTAL>>>(Pp, Vtp, nullptr, Y, NS, BSN, NE, NS,
                                             (long long)NS * NS, (long long)NS,
                                             (long long)NS * NE, 1.f);
    }
}

// round 4
// speedup vs baseline: 1.9759x; 1.3277x over previous
#include <cuda_runtime.h>
#include <cuda_bf16.h>
#include <math.h>
#include <stdint.h>

#define NB 4
#define NS 2048
#define NE 1024
#define BSN (NB * NS)

// ---------------- persistent scratch (no cudaMalloc allowed) ----------------
__device__ __nv_bfloat16 g_Xhi[BSN * NE], g_Xlo[BSN * NE];            // 16MB x2
__device__ __nv_bfloat16 g_Whi[3 * NE * NE], g_Wlo[3 * NE * NE];      //  6MB x2
__device__ __nv_bfloat16 g_Qhi[BSN * NE], g_Qlo[BSN * NE];            // 16MB x2
__device__ __nv_bfloat16 g_Khi[BSN * NE], g_Klo[BSN * NE];            // 16MB x2
__device__ __nv_bfloat16 g_Vthi[(size_t)NE * BSN], g_Vtlo[(size_t)NE * BSN];
__device__ float         g_P[(size_t)NB * NS * NS];                    // 64MB
__device__ __nv_bfloat16 g_Phi[(size_t)NB * NS * NS], g_Plo[(size_t)NB * NS * NS];

// ---------------- helpers ----------------
__device__ __forceinline__ uint32_t smem_u32(const void* p) {
    uint32_t a;
    asm("{ .reg .u64 t; cvta.to.shared.u64 t, %1; cvt.u32.u64 %0, t; }" : "=r"(a) : "l"(p));
    return a;
}
__device__ __forceinline__ void ldsm4(uint32_t* r, uint32_t addr) {
    asm volatile("ldmatrix.sync.aligned.m8n8.x4.shared.b16 {%0,%1,%2,%3}, [%4];"
                 : "=r"(r[0]), "=r"(r[1]), "=r"(r[2]), "=r"(r[3]) : "r"(addr));
}
__device__ __forceinline__ void mma16816(float* c, const uint32_t* a, const uint32_t* b) {
    asm volatile("mma.sync.aligned.m16n8k16.row.col.f32.bf16.bf16.f32 "
                 "{%0,%1,%2,%3}, {%4,%5,%6,%7}, {%8,%9}, {%0,%1,%2,%3};"
                 : "+f"(c[0]), "+f"(c[1]), "+f"(c[2]), "+f"(c[3])
                 : "r"(a[0]), "r"(a[1]), "r"(a[2]), "r"(a[3]), "r"(b[0]), "r"(b[1]));
}
__device__ __forceinline__ void cpa16(uint32_t s, const void* g) {
    asm volatile("cp.async.cg.shared.global [%0], [%1], 16;" :: "r"(s), "l"(g));
}
#define CP_COMMIT() asm volatile("cp.async.commit_group;" ::: "memory")
#define CP_WAIT(N)  asm volatile("cp.async.wait_group %0;" :: "n"(N) : "memory")

__device__ __forceinline__ uint32_t pack_bf2(float a, float b) {
    unsigned short ua = __bfloat16_as_ushort(__float2bfloat16(a));
    unsigned short ub = __bfloat16_as_ushort(__float2bfloat16(b));
    return (uint32_t)ua | ((uint32_t)ub << 16);
}
// split two floats -> (hi pair, lo pair)
__device__ __forceinline__ void split2(float a, float b, uint32_t& h, uint32_t& l) {
    h = pack_bf2(a, b);
    float ha = __uint_as_float(h << 16);
    float hb = __uint_as_float(h & 0xFFFF0000u);
    l = pack_bf2(a - ha, b - hb);
}

// smem tile: 128 rows x 32 bf16, padded rows of 80 B
#define ROWB 80
#define T_A_HI 0
#define T_A_LO 10240
#define T_B_HI 20480
#define T_B_LO 30720
#define STAGE  40960
#define NSTAGE 4
#define SMEM_TOTAL (NSTAGE * STAGE)   // 160 KB

// ---------------------------------------------------------------------------
// HMMA GEMM, bf16 hi/lo 3-term split, NT: C = alpha*A*B^T (+bias)
// A,B given as pre-split bf16 hi/lo, K-major. 128x128 tile, BK=32, 8 warps.
// BIAS: 0 none, 1 bias[col], 2 bias[row].  OUTMODE: 0 fp32 C, 1 bf16 hi/lo C.
// ---------------------------------------------------------------------------
template <int BIAS, int OUTMODE>
__global__ void __launch_bounds__(256, 1)
tcgemm(const __nv_bfloat16* __restrict__ Ahi, const __nv_bfloat16* __restrict__ Alo,
       const __nv_bfloat16* __restrict__ Bhi, const __nv_bfloat16* __restrict__ Blo,
       const float* __restrict__ bias,
       float* __restrict__ C,
       __nv_bfloat16* __restrict__ Chi, __nv_bfloat16* __restrict__ Clo,
       int lda, int ldb, int ldc, int Kdim,
       long long sA, long long sB, long long sC, float alpha)
{
    extern __shared__ char smem[];
    const uint32_t sb = smem_u32(smem);
    const int tid = threadIdx.x;
    const int lane = tid & 31;
    const int wid = tid >> 5;
    const int warpM = (wid & 3) * 32;
    const int warpN = (wid >> 2) * 64;

    const long long aoff = (long long)blockIdx.z * sA + (long long)(blockIdx.y * 128) * lda;
    const long long boff = (long long)blockIdx.z * sB + (long long)(blockIdx.x * 128) * ldb;

    float acc[2][8][4];
#pragma unroll
    for (int m = 0; m < 2; m++)
#pragma unroll
        for (int n = 0; n < 8; n++)
#pragma unroll
            for (int q = 0; q < 4; q++) acc[m][n][q] = 0.f;

    auto issueStage = [&](int s, int kt) {
        const uint32_t st = sb + s * STAGE;
#pragma unroll
        for (int p = 0; p < 2; p++) {
            const int i = tid + p * 256;           // 0..511
            const int r = i >> 2, q = i & 3;       // row, 16B-quad
            const uint32_t so = (uint32_t)(r * ROWB + q * 16);
            const long long ga = aoff + (long long)r * lda + kt + q * 8;
            const long long gb = boff + (long long)r * ldb + kt + q * 8;
            cpa16(st + T_A_HI + so, Ahi + ga);
            cpa16(st + T_A_LO + so, Alo + ga);
            cpa16(st + T_B_HI + so, Bhi + gb);
            cpa16(st + T_B_LO + so, Blo + gb);
        }
    };

    const uint32_t rA = (uint32_t)(warpM + (lane & 15));
    const uint32_t rB = (uint32_t)(warpN + (lane & 15));

    auto compute = [&](int s) {
        const uint32_t stb = sb + s * STAGE;
#pragma unroll
        for (int kh = 0; kh < 2; kh++) {
            const uint32_t cb = ((lane >> 4) * 8 + kh * 16) * 2;
            uint32_t ahi[2][4], alo[2][4], bhi[8][2], blo[8][2];
#pragma unroll
            for (int mt = 0; mt < 2; mt++) {
                ldsm4(ahi[mt], stb + T_A_HI + (rA + mt * 16) * ROWB + cb);
                ldsm4(alo[mt], stb + T_A_LO + (rA + mt * 16) * ROWB + cb);
            }
#pragma unroll
            for (int np = 0; np < 4; np++) {
                uint32_t t[4];
                ldsm4(t, stb + T_B_HI + (rB + np * 16) * ROWB + cb);
                bhi[2 * np][0] = t[0]; bhi[2 * np][1] = t[2];
                bhi[2 * np + 1][0] = t[1]; bhi[2 * np + 1][1] = t[3];
                ldsm4(t, stb + T_B_LO + (rB + np * 16) * ROWB + cb);
                blo[2 * np][0] = t[0]; blo[2 * np][1] = t[2];
                blo[2 * np + 1][0] = t[1]; blo[2 * np + 1][1] = t[3];
            }
            // 3 split terms, grouped so each acc is touched every 16 MMAs
#pragma unroll
            for (int mt = 0; mt < 2; mt++)
#pragma unroll
                for (int nt = 0; nt < 8; nt++) mma16816(acc[mt][nt], ahi[mt], bhi[nt]);
#pragma unroll
            for (int mt = 0; mt < 2; mt++)
#pragma unroll
                for (int nt = 0; nt < 8; nt++) mma16816(acc[mt][nt], ahi[mt], blo[nt]);
#pragma unroll
            for (int mt = 0; mt < 2; mt++)
#pragma unroll
                for (int nt = 0; nt < 8; nt++) mma16816(acc[mt][nt], alo[mt], bhi[nt]);
        }
    };

    const int CH = Kdim >> 5;
    issueStage(0, 0);   CP_COMMIT();
    issueStage(1, 32);  CP_COMMIT();
    issueStage(2, 64);  CP_COMMIT();

    for (int c = 0; c < CH; c++) {
        if (c + 3 < CH) { CP_WAIT(2); } else { CP_WAIT(0); }
        __syncthreads();
        if (c + 3 < CH) { issueStage((c + 3) & 3, (c + 3) * 32); CP_COMMIT(); }
        compute(c & 3);
    }

    // ---- epilogue ----
    const int g = lane >> 2, tg = lane & 3;
#pragma unroll
    for (int mt = 0; mt < 2; mt++) {
        const int row = blockIdx.y * 128 + warpM + mt * 16 + g;
        float rb0 = 0.f, rb8 = 0.f;
        if (BIAS == 2) { rb0 = bias[row]; rb8 = bias[row + 8]; }
#pragma unroll
        for (int nt = 0; nt < 8; nt++) {
            const int col = blockIdx.x * 128 + warpN + nt * 8 + tg * 2;
            float b0 = 0.f, b1 = 0.f;
            if (BIAS == 1) { b0 = bias[col]; b1 = bias[col + 1]; }
            float c0 = acc[mt][nt][0] * alpha;
            float c1 = acc[mt][nt][1] * alpha;
            float c2 = acc[mt][nt][2] * alpha;
            float c3 = acc[mt][nt][3] * alpha;
            if (BIAS == 1) { c0 += b0; c1 += b1; c2 += b0; c3 += b1; }
            if (BIAS == 2) { c0 += rb0; c1 += rb0; c2 += rb8; c3 += rb8; }
            const long long i0 = (long long)blockIdx.z * sC + (long long)row * ldc + col;
            const long long i1 = i0 + (long long)8 * ldc;
            if (OUTMODE == 0) {
                *(float2*)(C + i0) = make_float2(c0, c1);
                *(float2*)(C + i1) = make_float2(c2, c3);
            } else {
                uint32_t h, l;
                split2(c0, c1, h, l);
                *(uint32_t*)(Chi + i0) = h; *(uint32_t*)(Clo + i0) = l;
                split2(c2, c3, h, l);
                *(uint32_t*)(Chi + i1) = h; *(uint32_t*)(Clo + i1) = l;
            }
        }
    }
}

// ---------------------------------------------------------------------------
// fp32 -> bf16 hi/lo split (vectorized, 4 elems/thread)
// ---------------------------------------------------------------------------
__global__ __launch_bounds__(256)
void splitkern(const float* __restrict__ x, __nv_bfloat16* __restrict__ hi,
               __nv_bfloat16* __restrict__ lo, int n4)
{
    const int i = blockIdx.x * 256 + threadIdx.x;
    if (i >= n4) return;
    const float4 v = ((const float4*)x)[i];
    uint32_t h01, l01, h23, l23;
    split2(v.x, v.y, h01, l01);
    split2(v.z, v.w, h23, l23);
    ((uint2*)hi)[i] = make_uint2(h01, h23);
    ((uint2*)lo)[i] = make_uint2(l01, l23);
}

// ---------------------------------------------------------------------------
// Row softmax over 2048, emits bf16 hi/lo. One block (256 thr) per row.
// ---------------------------------------------------------------------------
__global__ __launch_bounds__(256)
void softmax2048(const float* __restrict__ P, __nv_bfloat16* __restrict__ Phi,
                 __nv_bfloat16* __restrict__ Plo)
{
    __shared__ float red[32];
    const float* p = P + (long long)blockIdx.x * NS;
    const int tid = threadIdx.x;

    float v[8];
    {
        const float4 a = *(const float4*)(p + tid * 8);
        const float4 b = *(const float4*)(p + tid * 8 + 4);
        v[0] = a.x; v[1] = a.y; v[2] = a.z; v[3] = a.w;
        v[4] = b.x; v[5] = b.y; v[6] = b.z; v[7] = b.w;
    }

    float m = v[0];
#pragma unroll
    for (int i = 1; i < 8; i++) m = fmaxf(m, v[i]);
#pragma unroll
    for (int o = 16; o > 0; o >>= 1) m = fmaxf(m, __shfl_xor_sync(0xffffffffu, m, o));
    if ((tid & 31) == 0) red[tid >> 5] = m;
    __syncthreads();
    if (tid < 32) {
        float t = (tid < 8) ? red[tid] : -INFINITY;
#pragma unroll
        for (int o = 4; o > 0; o >>= 1) t = fmaxf(t, __shfl_xor_sync(0xffffffffu, t, o));
        if (tid == 0) red[0] = t;
    }
    __syncthreads();
    m = red[0];
    __syncthreads();

    float s = 0.f;
#pragma unroll
    for (int i = 0; i < 8; i++) { v[i] = __expf(v[i] - m); s += v[i]; }
#pragma unroll
    for (int o = 16; o > 0; o >>= 1) s += __shfl_xor_sync(0xffffffffu, s, o);
    if ((tid & 31) == 0) red[tid >> 5] = s;
    __syncthreads();
    if (tid < 32) {
        float t = (tid < 8) ? red[tid] : 0.f;
#pragma unroll
        for (int o = 4; o > 0; o >>= 1) t += __shfl_xor_sync(0xffffffffu, t, o);
        if (tid == 0) red[0] = t;
    }
    __syncthreads();
    const float inv = 1.f / red[0];

    uint4 H, L;
    split2(v[0] * inv, v[1] * inv, H.x, L.x);
    split2(v[2] * inv, v[3] * inv, H.y, L.y);
    split2(v[4] * inv, v[5] * inv, H.z, L.z);
    split2(v[6] * inv, v[7] * inv, H.w, L.w);
    const long long o = (long long)blockIdx.x * NS + tid * 8;
    *(uint4*)(Phi + o) = H;
    *(uint4*)(Plo + o) = L;
}

// ---------------------------------------------------------------------------
// Launcher.
// ---------------------------------------------------------------------------
extern "C" void kernel_launch(void* const* d_in, const int* in_sizes, int n_in,
                              void* d_out, int out_size)
{
    const float* X  = (const float*)d_in[0];
    const float* Wk = (const float*)d_in[1];
    const float* bk = (const float*)d_in[2];
    const float* Wq = (const float*)d_in[3];
    const float* bq = (const float*)d_in[4];
    const float* Wv = (const float*)d_in[5];
    const float* bv = (const float*)d_in[6];
    float* Y = (float*)d_out;

    __nv_bfloat16 *Xhi, *Xlo, *Whi, *Wlo, *Qhi, *Qlo, *Khi, *Klo, *Vthi, *Vtlo, *Phi, *Plo;
    float* Pp;
    cudaGetSymbolAddress((void**)&Xhi, g_Xhi);   cudaGetSymbolAddress((void**)&Xlo, g_Xlo);
    cudaGetSymbolAddress((void**)&Whi, g_Whi);   cudaGetSymbolAddress((void**)&Wlo, g_Wlo);
    cudaGetSymbolAddress((void**)&Qhi, g_Qhi);   cudaGetSymbolAddress((void**)&Qlo, g_Qlo);
    cudaGetSymbolAddress((void**)&Khi, g_Khi);   cudaGetSymbolAddress((void**)&Klo, g_Klo);
    cudaGetSymbolAddress((void**)&Vthi, g_Vthi); cudaGetSymbolAddress((void**)&Vtlo, g_Vtlo);
    cudaGetSymbolAddress((void**)&Phi, g_Phi);   cudaGetSymbolAddress((void**)&Plo, g_Plo);
    cudaGetSymbolAddress((void**)&Pp, g_P);

    cudaFuncSetAttribute(tcgemm<0, 0>, cudaFuncAttributeMaxDynamicSharedMemorySize, SMEM_TOTAL);
    cudaFuncSetAttribute(tcgemm<1, 1>, cudaFuncAttributeMaxDynamicSharedMemorySize, SMEM_TOTAL);
    cudaFuncSetAttribute(tcgemm<2, 1>, cudaFuncAttributeMaxDynamicSharedMemorySize, SMEM_TOTAL);

    const dim3 blk(256);
    const int WN = NE * NE;

    // split inputs into bf16 hi/lo
    splitkern<<<(BSN * NE / 4 + 255) / 256, blk>>>(X, Xhi, Xlo, BSN * NE / 4);
    splitkern<<<(WN / 4 + 255) / 256, blk>>>(Wk, Whi,          Wlo,          WN / 4);
    splitkern<<<(WN / 4 + 255) / 256, blk>>>(Wq, Whi + WN,     Wlo + WN,     WN / 4);
    splitkern<<<(WN / 4 + 255) / 256, blk>>>(Wv, Whi + 2 * WN, Wlo + 2 * WN, WN / 4);

    // K, Q projections -> bf16 hi/lo directly
    {
        dim3 grid(NE / 128, BSN / 128, 1);
        tcgemm<1, 1><<<grid, blk, SMEM_TOTAL>>>(Xhi, Xlo, Whi, Wlo, bk,
                                                nullptr, Khi, Klo,
                                                NE, NE, NE, NE, 0, 0, 0, 1.f);
        tcgemm<1, 1><<<grid, blk, SMEM_TOTAL>>>(Xhi, Xlo, Whi + WN, Wlo + WN, bq,
                                                nullptr, Qhi, Qlo,
                                                NE, NE, NE, NE, 0, 0, 0, 1.f);
    }
    // Vt = Wv @ X^T + bv(row) -> bf16 hi/lo [E, B*S]
    {
        dim3 grid(BSN / 128, NE / 128, 1);
        tcgemm<2, 1><<<grid, blk, SMEM_TOTAL>>>(Whi + 2 * WN, Wlo + 2 * WN, Xhi, Xlo, bv,
                                                nullptr, Vthi, Vtlo,
                                                NE, NE, BSN, NE, 0, 0, 0, 1.f);
    }
    // Scores: P[b,j,i] = Q_j . K_i / sqrt(S), fp32
    {
        dim3 grid(NS / 128, NS / 128, NB);
        const float alpha = rsqrtf((float)NS);
        tcgemm<0, 0><<<grid, blk, SMEM_TOTAL>>>(Qhi, Qlo, Khi, Klo, nullptr,
                                                Pp, nullptr, nullptr,
                                                NE, NE, NS, NE,
                                                (long long)NS * NE, (long long)NS * NE,
                                                (long long)NS * NS, alpha);
    }
    // Softmax over key index i -> bf16 hi/lo
    softmax2048<<<NB * NS, blk>>>(Pp, Phi, Plo);

    // Y = P @ Vt^T, fp32 out
    {
        dim3 grid(NE / 128, NS / 128, NB);
        tcgemm<0, 0><<<grid, blk, SMEM_TOTAL>>>(Phi, Plo, Vthi, Vtlo, nullptr,
                                                Y, nullptr, nullptr,
                                                NS, BSN, NE, NS,
                                                (long long)NS * NS, (long long)NS,
                                                (long long)NS * NE, 1.f);
    }
}

// round 5
// speedup vs baseline: 2.1742x; 1.1003x over previous
#include <cuda_runtime.h>
#include <cuda_bf16.h>
#include <math.h>
#include <stdint.h>

#define NB 4
#define NS 2048
#define NE 1024
#define BSN (NB * NS)

// ---------------- persistent scratch (no cudaMalloc allowed) ----------------
__device__ __nv_bfloat16 g_Xhi[BSN * NE], g_Xlo[BSN * NE];
__device__ __nv_bfloat16 g_Whi[3 * NE * NE], g_Wlo[3 * NE * NE];
__device__ __nv_bfloat16 g_Qhi[BSN * NE], g_Qlo[BSN * NE];
__device__ __nv_bfloat16 g_Khi[BSN * NE], g_Klo[BSN * NE];
__device__ __nv_bfloat16 g_Vthi[(size_t)NE * BSN], g_Vtlo[(size_t)NE * BSN];
__device__ float         g_P[(size_t)NB * NS * NS];
__device__ __nv_bfloat16 g_Phi[(size_t)NB * NS * NS], g_Plo[(size_t)NB * NS * NS];

// ---------------- helpers ----------------
__device__ __forceinline__ uint32_t smem_u32(const void* p) {
    uint32_t a;
    asm("{ .reg .u64 t; cvta.to.shared.u64 t, %1; cvt.u32.u64 %0, t; }" : "=r"(a) : "l"(p));
    return a;
}
__device__ __forceinline__ void ldsm4(uint32_t* r, uint32_t addr) {
    asm volatile("ldmatrix.sync.aligned.m8n8.x4.shared.b16 {%0,%1,%2,%3}, [%4];"
                 : "=r"(r[0]), "=r"(r[1]), "=r"(r[2]), "=r"(r[3]) : "r"(addr));
}
__device__ __forceinline__ void mma16816(float* c, const uint32_t* a, const uint32_t* b) {
    asm volatile("mma.sync.aligned.m16n8k16.row.col.f32.bf16.bf16.f32 "
                 "{%0,%1,%2,%3}, {%4,%5,%6,%7}, {%8,%9}, {%0,%1,%2,%3};"
                 : "+f"(c[0]), "+f"(c[1]), "+f"(c[2]), "+f"(c[3])
                 : "r"(a[0]), "r"(a[1]), "r"(a[2]), "r"(a[3]), "r"(b[0]), "r"(b[1]));
}
__device__ __forceinline__ void cpa16(uint32_t s, const void* g) {
    asm volatile("cp.async.cg.shared.global [%0], [%1], 16;" :: "r"(s), "l"(g));
}
#define CP_COMMIT() asm volatile("cp.async.commit_group;" ::: "memory")
#define CP_WAIT(N)  asm volatile("cp.async.wait_group %0;" :: "n"(N) : "memory")

__device__ __forceinline__ uint32_t pack_bf2(float a, float b) {
    unsigned short ua = __bfloat16_as_ushort(__float2bfloat16(a));
    unsigned short ub = __bfloat16_as_ushort(__float2bfloat16(b));
    return (uint32_t)ua | ((uint32_t)ub << 16);
}
__device__ __forceinline__ void split2(float a, float b, uint32_t& h, uint32_t& l) {
    h = pack_bf2(a, b);
    float ha = __uint_as_float(h << 16);
    float hb = __uint_as_float(h & 0xFFFF0000u);
    l = pack_bf2(a - ha, b - hb);
}

// smem tile: 128 rows x 64 bf16 (128 B) padded to 144 B per row.
#define ROWB 144
#define T_A_HI 0
#define T_A_LO 18432
#define T_B_HI 36864
#define T_B_LO 55296
#define STAGE  73728
#define NSTAGE 3
#define SMEM_TOTAL (NSTAGE * STAGE)   // 216 KB

// ---------------------------------------------------------------------------
// HMMA GEMM, bf16 hi/lo 3-term split, NT: C = alpha*A*B^T (+bias)
// 128x128 CTA tile, BK=64, 512 threads (16 warps, 4x4), warp tile 32x32.
// BIAS: 0 none, 1 bias[col], 2 bias[row].  OUTMODE: 0 fp32 C, 1 bf16 hi/lo C.
// ---------------------------------------------------------------------------
template <int BIAS, int OUTMODE>
__global__ void __launch_bounds__(512, 1)
tcgemm(const __nv_bfloat16* __restrict__ Ahi, const __nv_bfloat16* __restrict__ Alo,
       const __nv_bfloat16* __restrict__ Bhi, const __nv_bfloat16* __restrict__ Blo,
       const float* __restrict__ bias,
       float* __restrict__ C,
       __nv_bfloat16* __restrict__ Chi, __nv_bfloat16* __restrict__ Clo,
       int lda, int ldb, int ldc, int Kdim,
       long long sA, long long sB, long long sC, float alpha)
{
    extern __shared__ char smem[];
    const uint32_t sb = smem_u32(smem);
    const int tid = threadIdx.x;
    const int lane = tid & 31;
    const int wid = tid >> 5;
    const int warpM = (wid & 3) * 32;     // 4 warps in M
    const int warpN = (wid >> 2) * 32;    // 4 warps in N

    const long long aoff = (long long)blockIdx.z * sA + (long long)(blockIdx.y * 128) * lda;
    const long long boff = (long long)blockIdx.z * sB + (long long)(blockIdx.x * 128) * ldb;

    float acc[2][4][4];
#pragma unroll
    for (int m = 0; m < 2; m++)
#pragma unroll
        for (int n = 0; n < 4; n++)
#pragma unroll
            for (int q = 0; q < 4; q++) acc[m][n][q] = 0.f;

    // stage load: 256 rows (A128 + B128) x 8 16B-quads = 2048 quads / 512 thr
    auto issueStage = [&](int s, int kt) {
        const uint32_t st = sb + s * STAGE;
#pragma unroll
        for (int p = 0; p < 2; p++) {
            const int i = tid + p * 512;
            const int r = i >> 3, q = i & 7;
            const uint32_t so = (uint32_t)(r * ROWB + q * 16);
            const long long ga = aoff + (long long)r * lda + kt + q * 8;
            const long long gb = boff + (long long)r * ldb + kt + q * 8;
            cpa16(st + T_A_HI + so, Ahi + ga);
            cpa16(st + T_A_LO + so, Alo + ga);
            cpa16(st + T_B_HI + so, Bhi + gb);
            cpa16(st + T_B_LO + so, Blo + gb);
        }
    };

    const uint32_t rA = (uint32_t)(warpM + (lane & 15));
    const uint32_t rB = (uint32_t)(warpN + (lane & 15));

    auto compute = [&](int s) {
        const uint32_t stb = sb + s * STAGE;
#pragma unroll
        for (int kh = 0; kh < 4; kh++) {
            const uint32_t cb = ((lane >> 4) * 8 + kh * 16) * 2;
            uint32_t ahi[2][4], alo[2][4], bhi[4][2], blo[4][2];
#pragma unroll
            for (int mt = 0; mt < 2; mt++) {
                ldsm4(ahi[mt], stb + T_A_HI + (rA + mt * 16) * ROWB + cb);
                ldsm4(alo[mt], stb + T_A_LO + (rA + mt * 16) * ROWB + cb);
            }
#pragma unroll
            for (int np = 0; np < 2; np++) {
                uint32_t t[4];
                ldsm4(t, stb + T_B_HI + (rB + np * 16) * ROWB + cb);
                bhi[2 * np][0] = t[0]; bhi[2 * np][1] = t[2];
                bhi[2 * np + 1][0] = t[1]; bhi[2 * np + 1][1] = t[3];
                ldsm4(t, stb + T_B_LO + (rB + np * 16) * ROWB + cb);
                blo[2 * np][0] = t[0]; blo[2 * np][1] = t[2];
                blo[2 * np + 1][0] = t[1]; blo[2 * np + 1][1] = t[3];
            }
#pragma unroll
            for (int mt = 0; mt < 2; mt++)
#pragma unroll
                for (int nt = 0; nt < 4; nt++) mma16816(acc[mt][nt], ahi[mt], bhi[nt]);
#pragma unroll
            for (int mt = 0; mt < 2; mt++)
#pragma unroll
                for (int nt = 0; nt < 4; nt++) mma16816(acc[mt][nt], ahi[mt], blo[nt]);
#pragma unroll
            for (int mt = 0; mt < 2; mt++)
#pragma unroll
                for (int nt = 0; nt < 4; nt++) mma16816(acc[mt][nt], alo[mt], bhi[nt]);
        }
    };

    const int CH = Kdim >> 6;      // BK = 64
    issueStage(0, 0);  CP_COMMIT();
    issueStage(1, 64); CP_COMMIT();

    for (int c = 0; c < CH; c++) {
        if (c + 1 < CH) { CP_WAIT(1); } else { CP_WAIT(0); }
        __syncthreads();
        if (c + 2 < CH) { issueStage((c + 2) % NSTAGE, (c + 2) * 64); CP_COMMIT(); }
        compute(c % NSTAGE);
        __syncthreads();
    }

    // ---- epilogue ----
    const int g = lane >> 2, tg = lane & 3;
#pragma unroll
    for (int mt = 0; mt < 2; mt++) {
        const int row = blockIdx.y * 128 + warpM + mt * 16 + g;
        float rb0 = 0.f, rb8 = 0.f;
        if (BIAS == 2) { rb0 = bias[row]; rb8 = bias[row + 8]; }
#pragma unroll
        for (int nt = 0; nt < 4; nt++) {
            const int col = blockIdx.x * 128 + warpN + nt * 8 + tg * 2;
            float b0 = 0.f, b1 = 0.f;
            if (BIAS == 1) { b0 = bias[col]; b1 = bias[col + 1]; }
            float c0 = acc[mt][nt][0] * alpha;
            float c1 = acc[mt][nt][1] * alpha;
            float c2 = acc[mt][nt][2] * alpha;
            float c3 = acc[mt][nt][3] * alpha;
            if (BIAS == 1) { c0 += b0; c1 += b1; c2 += b0; c3 += b1; }
            if (BIAS == 2) { c0 += rb0; c1 += rb0; c2 += rb8; c3 += rb8; }
            const long long i0 = (long long)blockIdx.z * sC + (long long)row * ldc + col;
            const long long i1 = i0 + (long long)8 * ldc;
            if (OUTMODE == 0) {
                *(float2*)(C + i0) = make_float2(c0, c1);
                *(float2*)(C + i1) = make_float2(c2, c3);
            } else {
                uint32_t h, l;
                split2(c0, c1, h, l);
                *(uint32_t*)(Chi + i0) = h; *(uint32_t*)(Clo + i0) = l;
                split2(c2, c3, h, l);
                *(uint32_t*)(Chi + i1) = h; *(uint32_t*)(Clo + i1) = l;
            }
        }
    }
}

// ---------------------------------------------------------------------------
// fp32 -> bf16 hi/lo split
// ---------------------------------------------------------------------------
__global__ __launch_bounds__(256)
void splitkern(const float* __restrict__ x, __nv_bfloat16* __restrict__ hi,
               __nv_bfloat16* __restrict__ lo, int n4)
{
    const int i = blockIdx.x * 256 + threadIdx.x;
    if (i >= n4) return;
    const float4 v = ((const float4*)x)[i];
    uint32_t h01, l01, h23, l23;
    split2(v.x, v.y, h01, l01);
    split2(v.z, v.w, h23, l23);
    ((uint2*)hi)[i] = make_uint2(h01, h23);
    ((uint2*)lo)[i] = make_uint2(l01, l23);
}

// ---------------------------------------------------------------------------
// Row softmax over 2048, emits bf16 hi/lo. One block (256 thr) per row.
// ---------------------------------------------------------------------------
__global__ __launch_bounds__(256)
void softmax2048(const float* __restrict__ P, __nv_bfloat16* __restrict__ Phi,
                 __nv_bfloat16* __restrict__ Plo)
{
    __shared__ float red[32];
    const float* p = P + (long long)blockIdx.x * NS;
    const int tid = threadIdx.x;

    float v[8];
    {
        const float4 a = *(const float4*)(p + tid * 8);
        const float4 b = *(const float4*)(p + tid * 8 + 4);
        v[0] = a.x; v[1] = a.y; v[2] = a.z; v[3] = a.w;
        v[4] = b.x; v[5] = b.y; v[6] = b.z; v[7] = b.w;
    }

    float m = v[0];
#pragma unroll
    for (int i = 1; i < 8; i++) m = fmaxf(m, v[i]);
#pragma unroll
    for (int o = 16; o > 0; o >>= 1) m = fmaxf(m, __shfl_xor_sync(0xffffffffu, m, o));
    if ((tid & 31) == 0) red[tid >> 5] = m;
    __syncthreads();
    if (tid < 32) {
        float t = (tid < 8) ? red[tid] : -INFINITY;
#pragma unroll
        for (int o = 4; o > 0; o >>= 1) t = fmaxf(t, __shfl_xor_sync(0xffffffffu, t, o));
        if (tid == 0) red[0] = t;
    }
    __syncthreads();
    m = red[0];
    __syncthreads();

    float s = 0.f;
#pragma unroll
    for (int i = 0; i < 8; i++) { v[i] = __expf(v[i] - m); s += v[i]; }
#pragma unroll
    for (int o = 16; o > 0; o >>= 1) s += __shfl_xor_sync(0xffffffffu, s, o);
    if ((tid & 31) == 0) red[tid >> 5] = s;
    __syncthreads();
    if (tid < 32) {
        float t = (tid < 8) ? red[tid] : 0.f;
#pragma unroll
        for (int o = 4; o > 0; o >>= 1) t += __shfl_xor_sync(0xffffffffu, t, o);
        if (tid == 0) red[0] = t;
    }
    __syncthreads();
    const float inv = 1.f / red[0];

    uint4 H, L;
    split2(v[0] * inv, v[1] * inv, H.x, L.x);
    split2(v[2] * inv, v[3] * inv, H.y, L.y);
    split2(v[4] * inv, v[5] * inv, H.z, L.z);
    split2(v[6] * inv, v[7] * inv, H.w, L.w);
    const long long o = (long long)blockIdx.x * NS + tid * 8;
    *(uint4*)(Phi + o) = H;
    *(uint4*)(Plo + o) = L;
}

// ---------------------------------------------------------------------------
// Launcher.
// ---------------------------------------------------------------------------
extern "C" void kernel_launch(void* const* d_in, const int* in_sizes, int n_in,
                              void* d_out, int out_size)
{
    const float* X  = (const float*)d_in[0];
    const float* Wk = (const float*)d_in[1];
    const float* bk = (const float*)d_in[2];
    const float* Wq = (const float*)d_in[3];
    const float* bq = (const float*)d_in[4];
    const float* Wv = (const float*)d_in[5];
    const float* bv = (const float*)d_in[6];
    float* Y = (float*)d_out;

    __nv_bfloat16 *Xhi, *Xlo, *Whi, *Wlo, *Qhi, *Qlo, *Khi, *Klo, *Vthi, *Vtlo, *Phi, *Plo;
    float* Pp;
    cudaGetSymbolAddress((void**)&Xhi, g_Xhi);   cudaGetSymbolAddress((void**)&Xlo, g_Xlo);
    cudaGetSymbolAddress((void**)&Whi, g_Whi);   cudaGetSymbolAddress((void**)&Wlo, g_Wlo);
    cudaGetSymbolAddress((void**)&Qhi, g_Qhi);   cudaGetSymbolAddress((void**)&Qlo, g_Qlo);
    cudaGetSymbolAddress((void**)&Khi, g_Khi);   cudaGetSymbolAddress((void**)&Klo, g_Klo);
    cudaGetSymbolAddress((void**)&Vthi, g_Vthi); cudaGetSymbolAddress((void**)&Vtlo, g_Vtlo);
    cudaGetSymbolAddress((void**)&Phi, g_Phi);   cudaGetSymbolAddress((void**)&Plo, g_Plo);
    cudaGetSymbolAddress((void**)&Pp, g_P);

    cudaFuncSetAttribute(tcgemm<0, 0>, cudaFuncAttributeMaxDynamicSharedMemorySize, SMEM_TOTAL);
    cudaFuncSetAttribute(tcgemm<1, 1>, cudaFuncAttributeMaxDynamicSharedMemorySize, SMEM_TOTAL);
    cudaFuncSetAttribute(tcgemm<2, 1>, cudaFuncAttributeMaxDynamicSharedMemorySize, SMEM_TOTAL);

    const int WN = NE * NE;

    // split inputs into bf16 hi/lo
    splitkern<<<(BSN * NE / 4 + 255) / 256, 256>>>(X, Xhi, Xlo, BSN * NE / 4);
    splitkern<<<(WN / 4 + 255) / 256, 256>>>(Wk, Whi,          Wlo,          WN / 4);
    splitkern<<<(WN / 4 + 255) / 256, 256>>>(Wq, Whi + WN,     Wlo + WN,     WN / 4);
    splitkern<<<(WN / 4 + 255) / 256, 256>>>(Wv, Whi + 2 * WN, Wlo + 2 * WN, WN / 4);

    const dim3 blk(512);

    // K, Q projections -> bf16 hi/lo directly
    {
        dim3 grid(NE / 128, BSN / 128, 1);
        tcgemm<1, 1><<<grid, blk, SMEM_TOTAL>>>(Xhi, Xlo, Whi, Wlo, bk,
                                                nullptr, Khi, Klo,
                                                NE, NE, NE, NE, 0, 0, 0, 1.f);
        tcgemm<1, 1><<<grid, blk, SMEM_TOTAL>>>(Xhi, Xlo, Whi + WN, Wlo + WN, bq,
                                                nullptr, Qhi, Qlo,
                                                NE, NE, NE, NE, 0, 0, 0, 1.f);
    }
    // Vt = Wv @ X^T + bv(row) -> bf16 hi/lo [E, B*S]
    {
        dim3 grid(BSN / 128, NE / 128, 1);
        tcgemm<2, 1><<<grid, blk, SMEM_TOTAL>>>(Whi + 2 * WN, Wlo + 2 * WN, Xhi, Xlo, bv,
                                                nullptr, Vthi, Vtlo,
                                                NE, NE, BSN, NE, 0, 0, 0, 1.f);
    }
    // Scores: P[b,j,i] = Q_j . K_i / sqrt(S), fp32
    {
        dim3 grid(NS / 128, NS / 128, NB);
        const float alpha = rsqrtf((float)NS);
        tcgemm<0, 0><<<grid, blk, SMEM_TOTAL>>>(Qhi, Qlo, Khi, Klo, nullptr,
                                                Pp, nullptr, nullptr,
                                                NE, NE, NS, NE,
                                                (long long)NS * NE, (long long)NS * NE,
                                                (long long)NS * NS, alpha);
    }
    // Softmax over key index i -> bf16 hi/lo
    softmax2048<<<NB * NS, 256>>>(Pp, Phi, Plo);

    // Y = P @ Vt^T, fp32 out
    {
        dim3 grid(NE / 128, NS / 128, NB);
        tcgemm<0, 0><<<grid, blk, SMEM_TOTAL>>>(Phi, Plo, Vthi, Vtlo, nullptr,
                                                Y, nullptr, nullptr,
                                                NS, BSN, NE, NS,
                                                (long long)NS * NS, (long long)NS,
                                                (long long)NS * NE, 1.f);
    }
}